// round 3
// baseline (speedup 1.0000x reference)
#include <cuda_runtime.h>
#include <cuda_bf16.h>
#include <math_constants.h>

#define ROWS 8192
#define COLS 8192
#define NG   64
#define TPB  32              // threads per block; each thread owns one row
#define CCHUNK 512           // columns per block
#define NCHUNK (COLS / CCHUNK)        // 16
#define NROWBLK (ROWS / TPB)          // 256
#define NOUT (ROWS * NG)              // 524288 per output tensor

// Global scratch: order-preserving uint-encoded fp32 min/max per (row, group).
// 2 x 2 MB static device arrays (L2-resident).
__device__ unsigned g_min_enc[NOUT];
__device__ unsigned g_max_enc[NOUT];

__device__ __forceinline__ unsigned enc_f32(float f) {
    unsigned u = __float_as_uint(f);
    return (u & 0x80000000u) ? ~u : (u | 0x80000000u);
}
__device__ __forceinline__ float dec_f32(unsigned e) {
    return (e & 0x80000000u) ? __uint_as_float(e ^ 0x80000000u)
                             : __uint_as_float(~e);
}

__global__ void obs_init_kernel() {
    int i = blockIdx.x * blockDim.x + threadIdx.x;
    if (i < NOUT) {
        g_min_enc[i] = 0xFFFFFFFFu;  // +max encoded
        g_max_enc[i] = 0u;           // -min encoded
    }
}

__global__ __launch_bounds__(TPB) void obs_main_kernel(
    const float* __restrict__ obs, const int* __restrict__ gidx)
{
    __shared__ __align__(16) int sg[CCHUNK];
    __shared__ float2 sacc[NG * TPB];   // [group][thread] {min,max}

    const int t   = threadIdx.x;
    const int c0  = blockIdx.x * CCHUNK;
    const int row = blockIdx.y * TPB + t;

    // Stage this chunk's group ids into SMEM (2 KB).
    {
        const int4* gv = (const int4*)(gidx + c0);
        #pragma unroll
        for (int i = t; i < CCHUNK / 4; i += TPB)
            ((int4*)sg)[i] = gv[i];
    }
    // Init private accumulators (group-major => bank = t, conflict-free).
    #pragma unroll
    for (int g = 0; g < NG; g++)
        sacc[g * TPB + t] = make_float2(CUDART_INF_F, -CUDART_INF_F);
    __syncthreads();

    const float4* rp = (const float4*)(obs + (size_t)row * COLS + c0);

    // 16 columns per iteration: 4x LDG.128 (64 B/thread in flight) + SMEM RMW.
    float4 a0 = rp[0], a1 = rp[1], a2 = rp[2], a3 = rp[3];

    #pragma unroll 1
    for (int j = 0; j < CCHUNK / 16; j++) {
        float4 n0, n1, n2, n3;
        if (j + 1 < CCHUNK / 16) {
            const float4* np = rp + (j + 1) * 4;
            n0 = np[0]; n1 = np[1]; n2 = np[2]; n3 = np[3];
        }
        const int cb = j * 16;
        int4 gq0 = *(const int4*)&sg[cb + 0];
        int4 gq1 = *(const int4*)&sg[cb + 4];
        int4 gq2 = *(const int4*)&sg[cb + 8];
        int4 gq3 = *(const int4*)&sg[cb + 12];

        #define UPD(VAL, G) do {                         \
            float2 _a = sacc[(G) * TPB + t];             \
            _a.x = fminf(_a.x, (VAL));                   \
            _a.y = fmaxf(_a.y, (VAL));                   \
            sacc[(G) * TPB + t] = _a;                    \
        } while (0)

        UPD(a0.x, gq0.x); UPD(a0.y, gq0.y); UPD(a0.z, gq0.z); UPD(a0.w, gq0.w);
        UPD(a1.x, gq1.x); UPD(a1.y, gq1.y); UPD(a1.z, gq1.z); UPD(a1.w, gq1.w);
        UPD(a2.x, gq2.x); UPD(a2.y, gq2.y); UPD(a2.z, gq2.z); UPD(a2.w, gq2.w);
        UPD(a3.x, gq3.x); UPD(a3.y, gq3.y); UPD(a3.z, gq3.z); UPD(a3.w, gq3.w);
        #undef UPD

        a0 = n0; a1 = n1; a2 = n2; a3 = n3;
    }

    // Flush private accumulators to global scratch via ordered-uint RED ops.
    unsigned* gm = g_min_enc + (size_t)row * NG;
    unsigned* gx = g_max_enc + (size_t)row * NG;
    #pragma unroll
    for (int g = 0; g < NG; g++) {
        float2 a = sacc[g * TPB + t];
        atomicMin(&gm[g], enc_f32(a.x));
        atomicMax(&gx[g], enc_f32(a.y));
    }
}

__global__ void obs_finalize_kernel(float* __restrict__ out) {
    int i = blockIdx.x * blockDim.x + threadIdx.x;
    if (i >= NOUT) return;
    float mn = fminf(dec_f32(g_min_enc[i]), 0.0f);
    float mx = fmaxf(dec_f32(g_max_enc[i]), 0.0f);
    // Match XLA: division by a compile-time constant is rewritten to
    // multiplication by the (rounded) reciprocal. 1/15 -> 0x3D888889.
    float sc = (mx - mn) * __uint_as_float(0x3D888889u);
    sc = fmaxf(sc, 1.1920929e-07f);
    // Runtime divisor: XLA emits exact div.rn.f32 here.
    float q  = __fdiv_rn(mn, sc);
    float zp = rintf(-8.0f - q);   // round-half-even == jnp.round
    zp = fminf(fmaxf(zp, -8.0f), 7.0f);
    out[i] = sc;                 // scale  [ROWS, NG]
    out[NOUT + i] = zp;          // zero_point (integral value, stored as f32)
}

extern "C" void kernel_launch(void* const* d_in, const int* in_sizes, int n_in,
                              void* d_out, int out_size) {
    const float* obs = (const float*)d_in[0];
    const int*   gidx = (const int*)d_in[1];
    float* out = (float*)d_out;

    obs_init_kernel<<<(NOUT + 255) / 256, 256>>>();

    dim3 grid(NCHUNK, NROWBLK);   // 16 x 256 = 4096 blocks
    obs_main_kernel<<<grid, TPB>>>(obs, gidx);

    obs_finalize_kernel<<<(NOUT + 255) / 256, 256>>>(out);
}

// round 4
// speedup vs baseline: 1.2467x; 1.2467x over previous
#include <cuda_runtime.h>
#include <cuda_bf16.h>
#include <math_constants.h>

#define ROWS 8192
#define COLS 8192
#define NG   64
#define TPB  32                       // one warp per block; thread = row
#define CCHUNK 1024                   // columns per block
#define NCHUNK (COLS / CCHUNK)        // 8
#define NROWBLK (ROWS / TPB)          // 256
#define NOUT (ROWS * NG)              // 524288 per output tensor

// Partial min/max per (chunk, row, group): plain stores, no atomics. 33.5 MB.
__device__ float2   g_part[(size_t)NCHUNK * ROWS * NG];
// Arrival counters per row-block (zero-initialized at load; last block resets).
__device__ unsigned g_cnt[NROWBLK];

__global__ __launch_bounds__(TPB) void obs_fused_kernel(
    const float* __restrict__ obs, const int* __restrict__ gidx,
    float* __restrict__ out)
{
    __shared__ __align__(16) int sg[CCHUNK];
    __shared__ float2 sacc[NG * TPB];   // [group][thread] {min,max}

    const int t   = threadIdx.x;
    const int bx  = blockIdx.x;         // chunk id
    const int by  = blockIdx.y;         // row-block id
    const int c0  = bx * CCHUNK;
    const int row = by * TPB + t;

    // Stage this chunk's group ids into SMEM (4 KB).
    {
        const int4* gv = (const int4*)(gidx + c0);
        #pragma unroll
        for (int i = t; i < CCHUNK / 4; i += TPB)
            ((int4*)sg)[i] = gv[i];
    }
    // Init private accumulators.
    #pragma unroll
    for (int g = 0; g < NG; g++)
        sacc[g * TPB + t] = make_float2(CUDART_INF_F, -CUDART_INF_F);
    __syncthreads();

    const float4* rp = (const float4*)(obs + (size_t)row * COLS + c0);

    // 16 columns per iteration: 4x LDG.128 prefetched + SMEM RMW.
    float4 a0 = rp[0], a1 = rp[1], a2 = rp[2], a3 = rp[3];

    #pragma unroll 1
    for (int j = 0; j < CCHUNK / 16; j++) {
        float4 n0, n1, n2, n3;
        if (j + 1 < CCHUNK / 16) {
            const float4* np = rp + (j + 1) * 4;
            n0 = np[0]; n1 = np[1]; n2 = np[2]; n3 = np[3];
        }
        const int cb = j * 16;
        int4 gq0 = *(const int4*)&sg[cb + 0];
        int4 gq1 = *(const int4*)&sg[cb + 4];
        int4 gq2 = *(const int4*)&sg[cb + 8];
        int4 gq3 = *(const int4*)&sg[cb + 12];

        #define UPD(VAL, G) do {                         \
            float2 _a = sacc[(G) * TPB + t];             \
            _a.x = fminf(_a.x, (VAL));                   \
            _a.y = fmaxf(_a.y, (VAL));                   \
            sacc[(G) * TPB + t] = _a;                    \
        } while (0)

        UPD(a0.x, gq0.x); UPD(a0.y, gq0.y); UPD(a0.z, gq0.z); UPD(a0.w, gq0.w);
        UPD(a1.x, gq1.x); UPD(a1.y, gq1.y); UPD(a1.z, gq1.z); UPD(a1.w, gq1.w);
        UPD(a2.x, gq2.x); UPD(a2.y, gq2.y); UPD(a2.z, gq2.z); UPD(a2.w, gq2.w);
        UPD(a3.x, gq3.x); UPD(a3.y, gq3.y); UPD(a3.z, gq3.z); UPD(a3.w, gq3.w);
        #undef UPD

        a0 = n0; a1 = n1; a2 = n2; a3 = n3;
    }

    // ---- Flush: vectorized plain stores to unique partial slots ----
    {
        float4* pp = (float4*)&g_part[((size_t)bx * ROWS + row) * NG];
        #pragma unroll
        for (int g = 0; g < NG; g += 2) {
            float2 a = sacc[g * TPB + t];
            float2 b = sacc[(g + 1) * TPB + t];
            pp[g >> 1] = make_float4(a.x, a.y, b.x, b.y);
        }
    }

    // ---- Arrival protocol: last block of this row-set finalizes ----
    __threadfence();
    unsigned old = 0;
    if (t == 0) old = atomicAdd(&g_cnt[by], 1u);
    old = __shfl_sync(0xFFFFFFFFu, old, 0);
    if (old != NCHUNK - 1) return;

    __threadfence();            // acquire: all blocks' partials now visible
    if (t == 0) g_cnt[by] = 0;  // self-reset for next graph replay

    const float rcp15 = __uint_as_float(0x3D888889u);  // XLA's rounded 1/15
    const int rbase = by * TPB;

    // Lane t owns groups {2t, 2t+1}; loop rows. Coalesced 512B float4 loads.
    for (int r = 0; r < TPB; r++) {
        size_t base = ((size_t)rbase + r) * NG;
        const float4* q0 = (const float4*)&g_part[base];
        float4 a = q0[t];   // {min(2t), max(2t), min(2t+1), max(2t+1)} chunk 0
        #pragma unroll
        for (int c = 1; c < NCHUNK; c++) {
            const float4* qc = (const float4*)&g_part[(size_t)c * ROWS * NG + base];
            float4 b = qc[t];
            a.x = fminf(a.x, b.x); a.y = fmaxf(a.y, b.y);
            a.z = fminf(a.z, b.z); a.w = fmaxf(a.w, b.w);
        }
        float mn0 = fminf(a.x, 0.0f), mx0 = fmaxf(a.y, 0.0f);
        float mn1 = fminf(a.z, 0.0f), mx1 = fmaxf(a.w, 0.0f);
        float sc0 = fmaxf((mx0 - mn0) * rcp15, 1.1920929e-07f);
        float sc1 = fmaxf((mx1 - mn1) * rcp15, 1.1920929e-07f);
        float zp0 = rintf(-8.0f - __fdiv_rn(mn0, sc0));
        float zp1 = rintf(-8.0f - __fdiv_rn(mn1, sc1));
        zp0 = fminf(fmaxf(zp0, -8.0f), 7.0f);
        zp1 = fminf(fmaxf(zp1, -8.0f), 7.0f);
        int o = (rbase + r) * NG + 2 * t;
        ((float2*)(out + o))[0]        = make_float2(sc0, sc1);   // scale
        ((float2*)(out + NOUT + o))[0] = make_float2(zp0, zp1);   // zero_point
    }
}

extern "C" void kernel_launch(void* const* d_in, const int* in_sizes, int n_in,
                              void* d_out, int out_size) {
    const float* obs  = (const float*)d_in[0];
    const int*   gidx = (const int*)d_in[1];
    float* out = (float*)d_out;

    dim3 grid(NCHUNK, NROWBLK);   // 8 x 256 = 2048 blocks
    obs_fused_kernel<<<grid, TPB>>>(obs, gidx, out);
}